// round 8
// baseline (speedup 1.0000x reference)
#include <cuda_runtime.h>

#define NB 16
#define NS 4096
#define NTOK (NB*NS)
#define CHUNK 256
#define KS 264             // padded f32 stride for K rows
#define VS 132             // padded u32 stride for V rows (bf16x2)
#define NCH (NS/CHUNK)

// scratch (device globals: no allocation allowed)
__device__ float g_qrow[NTOK*8];            // tf32(q*log2e/sqrt2) [b][s][w] (Q operand)
__device__ float g_qcol[NB*8*NS];           // tf32(q)             [b][w][t] (K operand)
__device__ unsigned short g_vhi[NB*8*NS];   // bf16 hi of q        [b][w][t] (V operand)
__device__ unsigned short g_vlo[NB*8*NS];   // bf16 lo residual

typedef unsigned int u32;
typedef unsigned long long u64;

__device__ __forceinline__ float ex2f(float x){float r; asm("ex2.approx.ftz.f32 %0,%1;":"=f"(r):"f"(x)); return r;}
__device__ __forceinline__ float tf32r(float x){u32 r; asm("cvt.rna.tf32.f32 %0,%1;":"=r"(r):"f"(x)); return __uint_as_float(r);}
// pack: result.lo = lo, result.hi = hi
__device__ __forceinline__ u32 pkbf(float hi, float lo){u32 r; asm("cvt.rn.bf16x2.f32 %0,%1,%2;":"=r"(r):"f"(hi),"f"(lo)); return r;}
__device__ __forceinline__ u64 pk2(float lo, float hi){u64 r; asm("mov.b64 %0,{%1,%2};":"=l"(r):"f"(lo),"f"(hi)); return r;}
__device__ __forceinline__ float2 upk2(u64 v){float2 f; asm("mov.b64 {%0,%1},%2;":"=f"(f.x),"=f"(f.y):"l"(v)); return f;}
__device__ __forceinline__ u64 fma2(u64 a,u64 b,u64 c){u64 d; asm("fma.rn.f32x2 %0,%1,%2,%3;":"=l"(d):"l"(a),"l"(b),"l"(c)); return d;}
__device__ __forceinline__ u64 mul2(u64 a,u64 b){u64 d; asm("mul.rn.f32x2 %0,%1,%2;":"=l"(d):"l"(a),"l"(b)); return d;}
__device__ __forceinline__ void cpa16(u32 dst, const void* src){
    asm volatile("cp.async.cg.shared.global [%0], [%1], 16;"::"r"(dst),"l"(src));
}
__device__ __forceinline__ void cpa_commit(){ asm volatile("cp.async.commit_group;"); }
__device__ __forceinline__ void cpa_wait1(){ asm volatile("cp.async.wait_group 1;"); }

__device__ __forceinline__ void mma_tf32(float* d, const u32* a, u32 b0, u32 b1){
    asm volatile("mma.sync.aligned.m16n8k8.row.col.f32.tf32.tf32.f32 "
        "{%0,%1,%2,%3},{%4,%5,%6,%7},{%8,%9},{%10,%11,%12,%13};"
        : "=f"(d[0]),"=f"(d[1]),"=f"(d[2]),"=f"(d[3])
        : "r"(a[0]),"r"(a[1]),"r"(a[2]),"r"(a[3]), "r"(b0),"r"(b1),
          "f"(0.f),"f"(0.f),"f"(0.f),"f"(0.f));
}
__device__ __forceinline__ void mma_bf16(float* d, const u32* a, u32 b0, u32 b1){
    asm volatile("mma.sync.aligned.m16n8k16.row.col.f32.bf16.bf16.f32 "
        "{%0,%1,%2,%3},{%4,%5,%6,%7},{%8,%9},{%0,%1,%2,%3};"
        : "+f"(d[0]),"+f"(d[1]),"+f"(d[2]),"+f"(d[3])
        : "r"(a[0]),"r"(a[1]),"r"(a[2]),"r"(a[3]), "r"(b0),"r"(b1));
}

// ---------------------------------------------------------------------------
// Kernel 1: quantum features (prefix cosine products).
//   Emits: Q (tf32, pre-scaled), K (tf32), V as bf16 hi/lo split.
// ---------------------------------------------------------------------------
__global__ void feat_kernel(const float* __restrict__ x, const float* __restrict__ theta)
{
    int tok = blockIdx.x*blockDim.x + threadIdx.x;
    float th[8];
    #pragma unroll
    for(int w=0;w<8;w++) th[w] = __ldg(&theta[w]);
    float4 x0 = *(const float4*)&x[tok*8];
    float4 x1 = *(const float4*)&x[tok*8+4];
    float c[8];
    c[0]=__cosf(x0.x+th[0]); c[1]=__cosf(x0.y+th[1]); c[2]=__cosf(x0.z+th[2]); c[3]=__cosf(x0.w+th[3]);
    c[4]=__cosf(x1.x+th[4]); c[5]=__cosf(x1.y+th[5]); c[6]=__cosf(x1.z+th[6]); c[7]=__cosf(x1.w+th[7]);
    float q[8];
    float p = c[0];
    #pragma unroll
    for(int w=1;w<8;w++){ p *= c[w]; q[w] = p; }
    float s = c[1];
    #pragma unroll
    for(int w=2;w<8;w++) s *= c[w];
    q[0] = s;                                   // CNOT-ring inverse image
    const float SC = 1.02013946f;               // log2(e)/sqrt(2)
    float qs[8];
    #pragma unroll
    for(int w=0;w<8;w++) qs[w]=tf32r(q[w]*SC);
    *(float4*)&g_qrow[tok*8]   = make_float4(qs[0],qs[1],qs[2],qs[3]);
    *(float4*)&g_qrow[tok*8+4] = make_float4(qs[4],qs[5],qs[6],qs[7]);
    int b = tok >> 12, t = tok & (NS-1);
    #pragma unroll
    for(int w=0;w<8;w++){
        float qv = q[w];
        g_qcol[(b*8+w)*NS + t] = tf32r(qv);
        u32 hp = pkbf(0.f, qv);                 // low half = bf16(qv)
        float hf = __uint_as_float(hp<<16);
        u32 lp = pkbf(0.f, qv - hf);
        g_vhi[(b*8+w)*NS + t] = (unsigned short)(hp & 0xffffu);
        g_vlo[(b*8+w)*NS + t] = (unsigned short)(lp & 0xffffu);
    }
}

// ---------------------------------------------------------------------------
// Kernel 2: flash attention via warp mma.sync + fused epilogue.
//   Per 16-t subtile: 2x tf32 mma -> S ;
//     hybrid exp: 6x ex2 (MUFU) + 1 packed f32x2 poly chain (FMA pipe, 2 elems);
//     4x cvt -> P bf16 ; 3x bf16 mma (num hi, num lo, den-with-ones).
//   den from tensor pipe -> no scalar FADDs, no final shuffles.
// ---------------------------------------------------------------------------
__global__ void __launch_bounds__(128) attn_kernel(const float* __restrict__ W,
                                                   const float* __restrict__ bias,
                                                   float* __restrict__ out)
{
    __shared__ __align__(16) float sk[2][8*KS];
    __shared__ __align__(16) u32   svh[2][8*VS];
    __shared__ __align__(16) u32   svl[2][8*VS];
    __shared__ float so[64*9];                   // o staging, stride 9

    const int b    = blockIdx.y;
    const int tid  = threadIdx.x;
    const int warp = tid >> 5, lane = tid & 31;
    const int g    = lane >> 2, c = lane & 3;
    const int row0 = blockIdx.x*64 + warp*16;

    const float* qc = &g_qcol[b*8*NS];
    const unsigned short* vh = &g_vhi[b*8*NS];
    const unsigned short* vl = &g_vlo[b*8*NS];

    u32 skb  = (u32)__cvta_generic_to_shared(&sk[0][0]);
    u32 svhb = (u32)__cvta_generic_to_shared(&svh[0][0]);
    u32 svlb = (u32)__cvta_generic_to_shared(&svl[0][0]);

    // Q fragment (held whole kernel)
    const float* qr = &g_qrow[(b*NS+row0)*8];
    u32 qa[4];
    qa[0] = __float_as_uint(qr[ g   *8 + c  ]);
    qa[1] = __float_as_uint(qr[(g+8)*8 + c  ]);
    qa[2] = __float_as_uint(qr[ g   *8 + c+4]);
    qa[3] = __float_as_uint(qr[(g+8)*8 + c+4]);

    float num[4]  = {0.f,0.f,0.f,0.f};
    float dden[4] = {0.f,0.f,0.f,0.f};           // den via ones-mma (cols redundant)
    const u32 ONEB = 0x3F803F80u;                // bf16x2 {1,1}

    // packed poly consts: exp(v*ln2) = (poly5(v*ln2/8))^8, |v*ln2/8| <= 0.71
    const u64 KK = pk2(0.08664339757f, 0.08664339757f);   // ln2/8
    const u64 C5 = pk2(8.4960e-3f, 8.4960e-3f);           // minimax-adj 1/120
    const u64 C4 = pk2(4.1666667e-2f, 4.1666667e-2f);
    const u64 C3 = pk2(0.16666667f, 0.16666667f);
    const u64 C2 = pk2(0.5f, 0.5f);
    const u64 ONE2 = pk2(1.f, 1.f);

    auto load_chunk = [&](int ch, int st){
        int t0 = ch*CHUNK;
        u32 kb = skb  + (u32)(st*8*KS)*4u;
        u32 hb = svhb + (u32)(st*8*VS)*4u;
        u32 lb = svlb + (u32)(st*8*VS)*4u;
        #pragma unroll
        for(int k=0;k<4;k++){
            int i = tid + k*128, row = i>>6, off = i&63;
            cpa16(kb + (u32)(row*KS+off*4)*4u, qc + row*NS + t0 + off*4);
        }
        #pragma unroll
        for(int k=0;k<2;k++){
            int i = tid + k*128, row = i>>5, off = i&31;
            cpa16(hb + (u32)(row*VS+off*4)*4u, vh + row*NS + t0 + off*8);
        }
        #pragma unroll
        for(int k=0;k<2;k++){
            int i = tid + k*128, row = i>>5, off = i&31;
            cpa16(lb + (u32)(row*VS+off*4)*4u, vl + row*NS + t0 + off*8);
        }
        cpa_commit();
    };

    load_chunk(0, 0);

    for(int ch=0; ch<NCH; ch++){
        int st = ch & 1;
        if(ch+1 < NCH) load_chunk(ch+1, (ch+1)&1);
        else           cpa_commit();           // keep wait count uniform
        cpa_wait1();
        __syncthreads();

        const float* K  = &sk[st][0];
        const u32*   VH = &svh[st][0];
        const u32*   VL = &svl[st][0];

        #pragma unroll 4
        for(int sub=0; sub<CHUNK/16; sub++){
            const int tb = sub*16;
            u32 kb00 = __float_as_uint(K[ c   *KS + tb + g    ]);
            u32 kb01 = __float_as_uint(K[(c+4)*KS + tb + g    ]);
            u32 kb10 = __float_as_uint(K[ c   *KS + tb + 8 + g]);
            u32 kb11 = __float_as_uint(K[(c+4)*KS + tb + 8 + g]);
            float dl[4], dr[4];
            mma_tf32(dl, qa, kb00, kb01);
            mma_tf32(dr, qa, kb10, kb11);
            // hybrid exp: dr[2],dr[3] on FMA pipe (packed poly), rest on MUFU
            u64 u = mul2(pk2(dr[2],dr[3]), KK);
            u64 p = fma2(u,C5,C4);
            p = fma2(p,u,C3);
            p = fma2(p,u,C2);
            p = fma2(p,u,ONE2);
            p = fma2(p,u,ONE2);
            p = mul2(p,p); p = mul2(p,p); p = mul2(p,p);   // ^8
            dl[0]=ex2f(dl[0]); dl[1]=ex2f(dl[1]); dl[2]=ex2f(dl[2]); dl[3]=ex2f(dl[3]);
            dr[0]=ex2f(dr[0]); dr[1]=ex2f(dr[1]);
            float2 pf = upk2(p);
            u32 pa[4];
            pa[0]=pkbf(dl[1],dl[0]); pa[1]=pkbf(dl[3],dl[2]);
            pa[2]=pkbf(dr[1],dr[0]); pa[3]=pkbf(pf.y,pf.x);
            int vi = g*VS + (tb>>1);
            u32 vh0 = VH[vi + c], vh1 = VH[vi + 4 + c];
            u32 vl0 = VL[vi + c], vl1 = VL[vi + 4 + c];
            mma_bf16(num,  pa, vh0, vh1);
            mma_bf16(num,  pa, vl0, vl1);
            mma_bf16(dden, pa, ONEB, ONEB);     // row sums -> den
        }
        __syncthreads();
    }

    float invl = 1.0f/dden[0], invh = 1.0f/dden[2];

    // stage normalized o tile: so[localRow][e], stride 9
    int lr = warp*16 + g;
    so[ lr   *9 + 2*c] = num[0]*invl;  so[ lr   *9 + 2*c+1] = num[1]*invl;
    so[(lr+8)*9 + 2*c] = num[2]*invh;  so[(lr+8)*9 + 2*c+1] = num[3]*invh;
    __syncthreads();

    // fused epilogue: out[b, e*512 + 8*bx + m, :] = bias + so[8m+j][e] . W[:,j]
    if(tid < 64){
        int e = tid >> 3, m = tid & 7;
        float y[8];
        #pragma unroll
        for(int j=0;j<8;j++) y[j] = so[(8*m+j)*9 + e];
        float r[8];
        #pragma unroll
        for(int ep=0;ep<8;ep++){
            float a = __ldg(&bias[ep]);
            #pragma unroll
            for(int j=0;j<8;j++) a = fmaf(y[j], __ldg(&W[ep*8+j]), a);
            r[ep]=a;
        }
        int i = e*512 + blockIdx.x*8 + m;
        float* op = &out[(b*NS + i)*8];
        *(float4*)op     = make_float4(r[0],r[1],r[2],r[3]);
        *(float4*)(op+4) = make_float4(r[4],r[5],r[6],r[7]);
    }
}

extern "C" void kernel_launch(void* const* d_in, const int* in_sizes, int n_in,
                              void* d_out, int out_size)
{
    const float* x     = (const float*)d_in[0];
    const float* theta = (const float*)d_in[1];
    const float* w     = (const float*)d_in[2];
    const float* bias  = (const float*)d_in[3];
    float* out = (float*)d_out;

    feat_kernel<<<NTOK/256, 256>>>(x, theta);
    dim3 g(NS/64, NB);
    attn_kernel<<<g, 128>>>(w, bias, out);
}

// round 9
// speedup vs baseline: 1.2655x; 1.2655x over previous
#include <cuda_runtime.h>

#define NB 16
#define NS 4096
#define NTOK (NB*NS)
#define CHUNK 256
#define KS 264             // padded f32 stride for K rows
#define VS 132             // padded u32 stride for V rows (bf16x2)
#define NCH (NS/CHUNK)

// scratch (device globals: no allocation allowed)
__device__ float g_qrow[NTOK*8];            // tf32(q*log2e/sqrt2) [b][s][w] (Q operand)
__device__ float g_qcol[NB*8*NS];           // tf32(q)             [b][w][t] (K operand)
__device__ unsigned short g_vhi[NB*8*NS];   // bf16(q)             [b][w][t] (V operand)

typedef unsigned int u32;

__device__ __forceinline__ float ex2f(float x){float r; asm("ex2.approx.ftz.f32 %0,%1;":"=f"(r):"f"(x)); return r;}
__device__ __forceinline__ float tf32r(float x){u32 r; asm("cvt.rna.tf32.f32 %0,%1;":"=r"(r):"f"(x)); return __uint_as_float(r);}
// pack: result.lo = lo, result.hi = hi
__device__ __forceinline__ u32 pkbf(float hi, float lo){u32 r; asm("cvt.rn.bf16x2.f32 %0,%1,%2;":"=r"(r):"f"(hi),"f"(lo)); return r;}
__device__ __forceinline__ void cpa16(u32 dst, const void* src){
    asm volatile("cp.async.cg.shared.global [%0], [%1], 16;"::"r"(dst),"l"(src));
}
__device__ __forceinline__ void cpa_commit(){ asm volatile("cp.async.commit_group;"); }
__device__ __forceinline__ void cpa_wait1(){ asm volatile("cp.async.wait_group 1;"); }

__device__ __forceinline__ void mma_tf32(float* d, const u32* a, u32 b0, u32 b1){
    asm volatile("mma.sync.aligned.m16n8k8.row.col.f32.tf32.tf32.f32 "
        "{%0,%1,%2,%3},{%4,%5,%6,%7},{%8,%9},{%10,%11,%12,%13};"
        : "=f"(d[0]),"=f"(d[1]),"=f"(d[2]),"=f"(d[3])
        : "r"(a[0]),"r"(a[1]),"r"(a[2]),"r"(a[3]), "r"(b0),"r"(b1),
          "f"(0.f),"f"(0.f),"f"(0.f),"f"(0.f));
}
__device__ __forceinline__ void mma_bf16(float* d, const u32* a, u32 b0, u32 b1){
    asm volatile("mma.sync.aligned.m16n8k16.row.col.f32.bf16.bf16.f32 "
        "{%0,%1,%2,%3},{%4,%5,%6,%7},{%8,%9},{%0,%1,%2,%3};"
        : "+f"(d[0]),"+f"(d[1]),"+f"(d[2]),"+f"(d[3])
        : "r"(a[0]),"r"(a[1]),"r"(a[2]),"r"(a[3]), "r"(b0),"r"(b1));
}

// ---------------------------------------------------------------------------
// Kernel 1: quantum features (prefix cosine products).
//   Emits: Q (tf32, pre-scaled), K (tf32), V (bf16).
// ---------------------------------------------------------------------------
__global__ void feat_kernel(const float* __restrict__ x, const float* __restrict__ theta)
{
    int tok = blockIdx.x*blockDim.x + threadIdx.x;
    float th[8];
    #pragma unroll
    for(int w=0;w<8;w++) th[w] = __ldg(&theta[w]);
    float4 x0 = *(const float4*)&x[tok*8];
    float4 x1 = *(const float4*)&x[tok*8+4];
    float c[8];
    c[0]=__cosf(x0.x+th[0]); c[1]=__cosf(x0.y+th[1]); c[2]=__cosf(x0.z+th[2]); c[3]=__cosf(x0.w+th[3]);
    c[4]=__cosf(x1.x+th[4]); c[5]=__cosf(x1.y+th[5]); c[6]=__cosf(x1.z+th[6]); c[7]=__cosf(x1.w+th[7]);
    float q[8];
    float p = c[0];
    #pragma unroll
    for(int w=1;w<8;w++){ p *= c[w]; q[w] = p; }
    float s = c[1];
    #pragma unroll
    for(int w=2;w<8;w++) s *= c[w];
    q[0] = s;                                   // CNOT-ring inverse image
    const float SC = 1.02013946f;               // log2(e)/sqrt(2)
    float qs[8];
    #pragma unroll
    for(int w=0;w<8;w++) qs[w]=tf32r(q[w]*SC);
    *(float4*)&g_qrow[tok*8]   = make_float4(qs[0],qs[1],qs[2],qs[3]);
    *(float4*)&g_qrow[tok*8+4] = make_float4(qs[4],qs[5],qs[6],qs[7]);
    int b = tok >> 12, t = tok & (NS-1);
    #pragma unroll
    for(int w=0;w<8;w++){
        float qv = q[w];
        g_qcol[(b*8+w)*NS + t] = tf32r(qv);
        g_vhi[(b*8+w)*NS + t] = (unsigned short)(pkbf(0.f, qv) & 0xffffu);
    }
}

// ---------------------------------------------------------------------------
// Kernel 2: flash attention via warp mma.sync + fused epilogue.
//   Per 16-t subtile: 2x tf32 mma -> S ; 8x ex2 -> P ; 4x cvt ;
//   1x bf16 mma (V bf16). 8 CTAs/SM capacity -> single wave of 1024 CTAs.
// ---------------------------------------------------------------------------
__global__ void __launch_bounds__(128, 8) attn_kernel(const float* __restrict__ W,
                                                      const float* __restrict__ bias,
                                                      float* __restrict__ out)
{
    __shared__ __align__(16) float sk[2][8*KS];
    __shared__ __align__(16) u32   svh[2][8*VS];
    __shared__ float so[64*9];                   // o staging, stride 9

    const int b    = blockIdx.y;
    const int tid  = threadIdx.x;
    const int warp = tid >> 5, lane = tid & 31;
    const int g    = lane >> 2, c = lane & 3;
    const int row0 = blockIdx.x*64 + warp*16;

    // hoisted chunk-load addressing (constants per thread)
    const int kr = tid >> 6, ko = tid & 63;      // K: rows kr+2k, off ko
    const int vr = tid >> 5, vo = tid & 31;      // V: rows vr+4k, off vo
    const float*          ksrc = &g_qcol[b*8*NS + kr*NS] + ko*4;
    const unsigned short* vsrc = &g_vhi [b*8*NS + vr*NS] + vo*8;
    u32 skb  = (u32)__cvta_generic_to_shared(&sk[0][0])  + (u32)(kr*KS + ko*4)*4u;
    u32 svhb = (u32)__cvta_generic_to_shared(&svh[0][0]) + (u32)(vr*VS + vo*4)*4u;
    const u32 KSTG = 8*KS*4u, VSTG = 8*VS*4u;

    // Q fragment (held whole kernel)
    const float* qr = &g_qrow[(b*NS+row0)*8];
    u32 qa[4];
    qa[0] = __float_as_uint(qr[ g   *8 + c  ]);
    qa[1] = __float_as_uint(qr[(g+8)*8 + c  ]);
    qa[2] = __float_as_uint(qr[ g   *8 + c+4]);
    qa[3] = __float_as_uint(qr[(g+8)*8 + c+4]);

    float num[4] = {0.f,0.f,0.f,0.f};
    float denl = 0.f, denh = 0.f;

    auto load_chunk = [&](int ch, int st){
        const float*          ks = ksrc + ch*CHUNK;
        const unsigned short* vs = vsrc + ch*CHUNK;
        u32 kb = skb  + (st ? KSTG : 0u);
        u32 hb = svhb + (st ? VSTG : 0u);
        #pragma unroll
        for(int k=0;k<4;k++) cpa16(kb + (u32)(2*k*KS)*4u, ks + 2*k*NS);
        #pragma unroll
        for(int k=0;k<2;k++) cpa16(hb + (u32)(4*k*VS)*4u, vs + 4*k*NS);
        cpa_commit();
    };

    load_chunk(0, 0);

    for(int ch=0; ch<NCH; ch++){
        int st = ch & 1;
        if(ch+1 < NCH) load_chunk(ch+1, (ch+1)&1);
        else           cpa_commit();           // keep wait count uniform
        cpa_wait1();
        __syncthreads();

        const float* K  = &sk[st][0];
        const u32*   VH = &svh[st][0];

        #pragma unroll 4
        for(int sub=0; sub<CHUNK/16; sub++){
            const int tb = sub*16;
            u32 kb00 = __float_as_uint(K[ c   *KS + tb + g    ]);
            u32 kb01 = __float_as_uint(K[(c+4)*KS + tb + g    ]);
            u32 kb10 = __float_as_uint(K[ c   *KS + tb + 8 + g]);
            u32 kb11 = __float_as_uint(K[(c+4)*KS + tb + 8 + g]);
            float dl[4], dr[4];
            mma_tf32(dl, qa, kb00, kb01);
            mma_tf32(dr, qa, kb10, kb11);
            dl[0]=ex2f(dl[0]); dl[1]=ex2f(dl[1]); dl[2]=ex2f(dl[2]); dl[3]=ex2f(dl[3]);
            dr[0]=ex2f(dr[0]); dr[1]=ex2f(dr[1]); dr[2]=ex2f(dr[2]); dr[3]=ex2f(dr[3]);
            denl += dl[0]+dl[1]+dr[0]+dr[1];
            denh += dl[2]+dl[3]+dr[2]+dr[3];
            u32 pa[4];
            pa[0]=pkbf(dl[1],dl[0]); pa[1]=pkbf(dl[3],dl[2]);
            pa[2]=pkbf(dr[1],dr[0]); pa[3]=pkbf(dr[3],dr[2]);
            int vi = g*VS + (tb>>1);
            mma_bf16(num, pa, VH[vi + c], VH[vi + 4 + c]);
        }
        __syncthreads();
    }

    denl += __shfl_xor_sync(0xffffffffu, denl, 1);
    denl += __shfl_xor_sync(0xffffffffu, denl, 2);
    denh += __shfl_xor_sync(0xffffffffu, denh, 1);
    denh += __shfl_xor_sync(0xffffffffu, denh, 2);
    float invl = 1.0f/denl, invh = 1.0f/denh;

    // stage normalized o tile: so[localRow][e], stride 9
    int lr = warp*16 + g;
    so[ lr   *9 + 2*c] = num[0]*invl;  so[ lr   *9 + 2*c+1] = num[1]*invl;
    so[(lr+8)*9 + 2*c] = num[2]*invh;  so[(lr+8)*9 + 2*c+1] = num[3]*invh;
    __syncthreads();

    // fused epilogue: out[b, e*512 + 8*bx + m, :] = bias + so[8m+j][e] . W[:,j]
    if(tid < 64){
        int e = tid >> 3, m = tid & 7;
        float y[8];
        #pragma unroll
        for(int j=0;j<8;j++) y[j] = so[(8*m+j)*9 + e];
        float r[8];
        #pragma unroll
        for(int ep=0;ep<8;ep++){
            float a = __ldg(&bias[ep]);
            #pragma unroll
            for(int j=0;j<8;j++) a = fmaf(y[j], __ldg(&W[ep*8+j]), a);
            r[ep]=a;
        }
        int i = e*512 + blockIdx.x*8 + m;
        float* op = &out[(b*NS + i)*8];
        *(float4*)op     = make_float4(r[0],r[1],r[2],r[3]);
        *(float4*)(op+4) = make_float4(r[4],r[5],r[6],r[7]);
    }
}

extern "C" void kernel_launch(void* const* d_in, const int* in_sizes, int n_in,
                              void* d_out, int out_size)
{
    const float* x     = (const float*)d_in[0];
    const float* theta = (const float*)d_in[1];
    const float* w     = (const float*)d_in[2];
    const float* bias  = (const float*)d_in[3];
    float* out = (float*)d_out;

    feat_kernel<<<NTOK/256, 256>>>(x, theta);
    dim3 g(NS/64, NB);
    attn_kernel<<<g, 128>>>(w, bias, out);
}

// round 10
// speedup vs baseline: 1.2984x; 1.0260x over previous
#include <cuda_runtime.h>

#define NB 16
#define NS 4096
#define NTOK (NB*NS)
#define CHUNK 256
#define KS 264             // padded f32 stride for K rows
#define VS 132             // padded u32 stride for V rows (bf16x2)
#define NCH (NS/CHUNK)

// scratch (device globals: no allocation allowed)
__device__ float g_qrow[NTOK*8];            // tf32(q*log2e/sqrt2) [b][s][w] (Q operand)
__device__ float g_qcol[NB*8*NS];           // tf32(q)             [b][w][t] (K operand)
__device__ unsigned short g_vhi[NB*8*NS];   // bf16(q)             [b][w][t] (V operand)

typedef unsigned int u32;

__device__ __forceinline__ float ex2f(float x){float r; asm("ex2.approx.ftz.f32 %0,%1;":"=f"(r):"f"(x)); return r;}
__device__ __forceinline__ float tf32r(float x){u32 r; asm("cvt.rna.tf32.f32 %0,%1;":"=r"(r):"f"(x)); return __uint_as_float(r);}
// pack: result.lo = lo, result.hi = hi
__device__ __forceinline__ u32 pkbf(float hi, float lo){u32 r; asm("cvt.rn.bf16x2.f32 %0,%1,%2;":"=r"(r):"f"(hi),"f"(lo)); return r;}
__device__ __forceinline__ void cpa16(u32 dst, const void* src){
    asm volatile("cp.async.cg.shared.global [%0], [%1], 16;"::"r"(dst),"l"(src));
}
__device__ __forceinline__ void cpa_commit(){ asm volatile("cp.async.commit_group;"); }
__device__ __forceinline__ void cpa_wait1(){ asm volatile("cp.async.wait_group 1;"); }

__device__ __forceinline__ void mma_tf32(float* d, const u32* a, u32 b0, u32 b1){
    asm volatile("mma.sync.aligned.m16n8k8.row.col.f32.tf32.tf32.f32 "
        "{%0,%1,%2,%3},{%4,%5,%6,%7},{%8,%9},{%10,%11,%12,%13};"
        : "=f"(d[0]),"=f"(d[1]),"=f"(d[2]),"=f"(d[3])
        : "r"(a[0]),"r"(a[1]),"r"(a[2]),"r"(a[3]), "r"(b0),"r"(b1),
          "f"(0.f),"f"(0.f),"f"(0.f),"f"(0.f));
}
__device__ __forceinline__ void mma_bf16(float* d, const u32* a, u32 b0, u32 b1){
    asm volatile("mma.sync.aligned.m16n8k16.row.col.f32.bf16.bf16.f32 "
        "{%0,%1,%2,%3},{%4,%5,%6,%7},{%8,%9},{%0,%1,%2,%3};"
        : "+f"(d[0]),"+f"(d[1]),"+f"(d[2]),"+f"(d[3])
        : "r"(a[0]),"r"(a[1]),"r"(a[2]),"r"(a[3]), "r"(b0),"r"(b1));
}

// ---------------------------------------------------------------------------
// Kernel 1: quantum features (prefix cosine products).
//   Emits: Q (tf32, pre-scaled), K (tf32), V (bf16).
// ---------------------------------------------------------------------------
__global__ void feat_kernel(const float* __restrict__ x, const float* __restrict__ theta)
{
    int tok = blockIdx.x*blockDim.x + threadIdx.x;
    float th[8];
    #pragma unroll
    for(int w=0;w<8;w++) th[w] = __ldg(&theta[w]);
    float4 x0 = *(const float4*)&x[tok*8];
    float4 x1 = *(const float4*)&x[tok*8+4];
    float c[8];
    c[0]=__cosf(x0.x+th[0]); c[1]=__cosf(x0.y+th[1]); c[2]=__cosf(x0.z+th[2]); c[3]=__cosf(x0.w+th[3]);
    c[4]=__cosf(x1.x+th[4]); c[5]=__cosf(x1.y+th[5]); c[6]=__cosf(x1.z+th[6]); c[7]=__cosf(x1.w+th[7]);
    float q[8];
    float p = c[0];
    #pragma unroll
    for(int w=1;w<8;w++){ p *= c[w]; q[w] = p; }
    float s = c[1];
    #pragma unroll
    for(int w=2;w<8;w++) s *= c[w];
    q[0] = s;                                   // CNOT-ring inverse image
    const float SC = 1.02013946f;               // log2(e)/sqrt(2)
    float qs[8];
    #pragma unroll
    for(int w=0;w<8;w++) qs[w]=tf32r(q[w]*SC);
    *(float4*)&g_qrow[tok*8]   = make_float4(qs[0],qs[1],qs[2],qs[3]);
    *(float4*)&g_qrow[tok*8+4] = make_float4(qs[4],qs[5],qs[6],qs[7]);
    int b = tok >> 12, t = tok & (NS-1);
    #pragma unroll
    for(int w=0;w<8;w++){
        float qv = q[w];
        g_qcol[(b*8+w)*NS + t] = tf32r(qv);
        g_vhi[(b*8+w)*NS + t] = (unsigned short)(pkbf(0.f, qv) & 0xffffu);
    }
}

// ---------------------------------------------------------------------------
// Kernel 2: flash attention via warp mma.sync + fused epilogue.
//   32 t per iteration as TWO independent subtile pipelines with separate
//   HMMA accumulators (num0/num1) and den chains -> breaks the D-operand
//   RAW serialization that bound the previous version.
// ---------------------------------------------------------------------------
__global__ void __launch_bounds__(128, 8) attn_kernel(const float* __restrict__ W,
                                                      const float* __restrict__ bias,
                                                      float* __restrict__ out)
{
    __shared__ __align__(16) float sk[2][8*KS];
    __shared__ __align__(16) u32   svh[2][8*VS];
    __shared__ float so[64*9];                   // o staging, stride 9

    const int b    = blockIdx.y;
    const int tid  = threadIdx.x;
    const int warp = tid >> 5, lane = tid & 31;
    const int g    = lane >> 2, c = lane & 3;
    const int row0 = blockIdx.x*64 + warp*16;

    // hoisted chunk-load addressing
    const int kr = tid >> 6, ko = tid & 63;
    const int vr = tid >> 5, vo = tid & 31;
    const float*          ksrc = &g_qcol[b*8*NS + kr*NS] + ko*4;
    const unsigned short* vsrc = &g_vhi [b*8*NS + vr*NS] + vo*8;
    u32 skb  = (u32)__cvta_generic_to_shared(&sk[0][0])  + (u32)(kr*KS + ko*4)*4u;
    u32 svhb = (u32)__cvta_generic_to_shared(&svh[0][0]) + (u32)(vr*VS + vo*4)*4u;
    const u32 KSTG = 8*KS*4u, VSTG = 8*VS*4u;

    // Q fragment (held whole kernel)
    const float* qr = &g_qrow[(b*NS+row0)*8];
    u32 qa[4];
    qa[0] = __float_as_uint(qr[ g   *8 + c  ]);
    qa[1] = __float_as_uint(qr[(g+8)*8 + c  ]);
    qa[2] = __float_as_uint(qr[ g   *8 + c+4]);
    qa[3] = __float_as_uint(qr[(g+8)*8 + c+4]);

    float num0[4] = {0.f,0.f,0.f,0.f};
    float num1[4] = {0.f,0.f,0.f,0.f};
    float d0l=0.f, d0h=0.f, d1l=0.f, d1h=0.f;

    auto load_chunk = [&](int ch, int st){
        const float*          ks = ksrc + ch*CHUNK;
        const unsigned short* vs = vsrc + ch*CHUNK;
        u32 kb = skb  + (st ? KSTG : 0u);
        u32 hb = svhb + (st ? VSTG : 0u);
        #pragma unroll
        for(int k=0;k<4;k++) cpa16(kb + (u32)(2*k*KS)*4u, ks + 2*k*NS);
        #pragma unroll
        for(int k=0;k<2;k++) cpa16(hb + (u32)(4*k*VS)*4u, vs + 4*k*NS);
        cpa_commit();
    };

    load_chunk(0, 0);

    for(int ch=0; ch<NCH; ch++){
        int st = ch & 1;
        if(ch+1 < NCH) load_chunk(ch+1, (ch+1)&1);
        else           cpa_commit();           // keep wait count uniform
        cpa_wait1();
        __syncthreads();

        const float* K  = &sk[st][0];
        const u32*   VH = &svh[st][0];

        #pragma unroll 2
        for(int pair=0; pair<CHUNK/32; pair++){
            const int tA = pair*32, tB = pair*32 + 16;
            // ---- pipeline A (subtile tA) ----
            u32 a00 = __float_as_uint(K[ c   *KS + tA + g    ]);
            u32 a01 = __float_as_uint(K[(c+4)*KS + tA + g    ]);
            u32 a10 = __float_as_uint(K[ c   *KS + tA + 8 + g]);
            u32 a11 = __float_as_uint(K[(c+4)*KS + tA + 8 + g]);
            // ---- pipeline B (subtile tB) ----
            u32 b00 = __float_as_uint(K[ c   *KS + tB + g    ]);
            u32 b01 = __float_as_uint(K[(c+4)*KS + tB + g    ]);
            u32 b10 = __float_as_uint(K[ c   *KS + tB + 8 + g]);
            u32 b11 = __float_as_uint(K[(c+4)*KS + tB + 8 + g]);

            float Al[4], Ar[4], Bl[4], Br[4];
            mma_tf32(Al, qa, a00, a01);
            mma_tf32(Ar, qa, a10, a11);
            mma_tf32(Bl, qa, b00, b01);
            mma_tf32(Br, qa, b10, b11);

            Al[0]=ex2f(Al[0]); Al[1]=ex2f(Al[1]); Al[2]=ex2f(Al[2]); Al[3]=ex2f(Al[3]);
            Ar[0]=ex2f(Ar[0]); Ar[1]=ex2f(Ar[1]); Ar[2]=ex2f(Ar[2]); Ar[3]=ex2f(Ar[3]);
            Bl[0]=ex2f(Bl[0]); Bl[1]=ex2f(Bl[1]); Bl[2]=ex2f(Bl[2]); Bl[3]=ex2f(Bl[3]);
            Br[0]=ex2f(Br[0]); Br[1]=ex2f(Br[1]); Br[2]=ex2f(Br[2]); Br[3]=ex2f(Br[3]);

            d0l += Al[0]+Al[1]+Ar[0]+Ar[1];
            d0h += Al[2]+Al[3]+Ar[2]+Ar[3];
            d1l += Bl[0]+Bl[1]+Br[0]+Br[1];
            d1h += Bl[2]+Bl[3]+Br[2]+Br[3];

            u32 pA[4], pB[4];
            pA[0]=pkbf(Al[1],Al[0]); pA[1]=pkbf(Al[3],Al[2]);
            pA[2]=pkbf(Ar[1],Ar[0]); pA[3]=pkbf(Ar[3],Ar[2]);
            pB[0]=pkbf(Bl[1],Bl[0]); pB[1]=pkbf(Bl[3],Bl[2]);
            pB[2]=pkbf(Br[1],Br[0]); pB[3]=pkbf(Br[3],Br[2]);

            int viA = g*VS + (tA>>1);
            int viB = g*VS + (tB>>1);
            mma_bf16(num0, pA, VH[viA + c], VH[viA + 4 + c]);
            mma_bf16(num1, pB, VH[viB + c], VH[viB + 4 + c]);
        }
        __syncthreads();
    }

    float denl = d0l + d1l, denh = d0h + d1h;
    denl += __shfl_xor_sync(0xffffffffu, denl, 1);
    denl += __shfl_xor_sync(0xffffffffu, denl, 2);
    denh += __shfl_xor_sync(0xffffffffu, denh, 1);
    denh += __shfl_xor_sync(0xffffffffu, denh, 2);
    float invl = 1.0f/denl, invh = 1.0f/denh;

    // stage normalized o tile: so[localRow][e], stride 9
    int lr = warp*16 + g;
    so[ lr   *9 + 2*c] = (num0[0]+num1[0])*invl;  so[ lr   *9 + 2*c+1] = (num0[1]+num1[1])*invl;
    so[(lr+8)*9 + 2*c] = (num0[2]+num1[2])*invh;  so[(lr+8)*9 + 2*c+1] = (num0[3]+num1[3])*invh;
    __syncthreads();

    // fused epilogue: out[b, e*512 + 8*bx + m, :] = bias + so[8m+j][e] . W[:,j]
    if(tid < 64){
        int e = tid >> 3, m = tid & 7;
        float y[8];
        #pragma unroll
        for(int j=0;j<8;j++) y[j] = so[(8*m+j)*9 + e];
        float r[8];
        #pragma unroll
        for(int ep=0;ep<8;ep++){
            float a = __ldg(&bias[ep]);
            #pragma unroll
            for(int j=0;j<8;j++) a = fmaf(y[j], __ldg(&W[ep*8+j]), a);
            r[ep]=a;
        }
        int i = e*512 + blockIdx.x*8 + m;
        float* op = &out[(b*NS + i)*8];
        *(float4*)op     = make_float4(r[0],r[1],r[2],r[3]);
        *(float4*)(op+4) = make_float4(r[4],r[5],r[6],r[7]);
    }
}

extern "C" void kernel_launch(void* const* d_in, const int* in_sizes, int n_in,
                              void* d_out, int out_size)
{
    const float* x     = (const float*)d_in[0];
    const float* theta = (const float*)d_in[1];
    const float* w     = (const float*)d_in[2];
    const float* bias  = (const float*)d_in[3];
    float* out = (float*)d_out;

    feat_kernel<<<NTOK/256, 256>>>(x, theta);
    dim3 g(NS/64, NB);
    attn_kernel<<<g, 128>>>(w, bias, out);
}